// round 4
// baseline (speedup 1.0000x reference)
#include <cuda_runtime.h>
#include <cuda_bf16.h>

#define B_ 2
#define S_ 2048
#define D_ 768
#define H_ 12
#define DH_ 64
#define SCALE_ 0.125f   // (1/sqrt(64)) * smoothing(1.0)

typedef unsigned long long ull;

// ----------------------------- scratch ------------------------------------
__device__ float g_bufQ[B_ * S_ * D_];
__device__ float g_bufK[B_ * S_ * D_];
__device__ float g_bufV[B_ * S_ * D_];
__device__ float g_bufQP[S_ * D_];
__device__ float g_bufKP[S_ * D_];
__device__ float g_qT[B_ * H_ * S_ * DH_];
__device__ float g_kT[B_ * H_ * S_ * DH_];
__device__ float g_vT[B_ * H_ * S_ * DH_];
__device__ float g_qpT[H_ * S_ * DH_];
__device__ float g_kpT[H_ * S_ * DH_];
__device__ float g_posP[(size_t)H_ * S_ * S_];        // prob_pos [h,i,j]
__device__ float g_blend[(size_t)B_ * H_ * S_ * S_];  // blended  [b,h,i,j]
__device__ float g_attnpre[B_ * S_ * D_];             // [b,s, h*64+d]

// --------------------------- f32x2 helpers --------------------------------
__device__ __forceinline__ ull fma2(ull a, ull b, ull c) {
    ull d; asm("fma.rn.f32x2 %0, %1, %2, %3;" : "=l"(d) : "l"(a), "l"(b), "l"(c));
    return d;
}
__device__ __forceinline__ ull dupf2(float x) {
    ull d; asm("mov.b64 %0, {%1, %1};" : "=l"(d) : "f"(x));
    return d;
}
__device__ __forceinline__ float sum2(ull v) {
    return __uint_as_float((unsigned)v) + __uint_as_float((unsigned)(v >> 32));
}

// --------------------- GEMM C[M,768] = A[M,768] @ W[768,768] ---------------
// BM=64 BN=64 BK=16, 256 threads, 4x4 micro-tile, FFMA2 packed along N.
__global__ __launch_bounds__(256) void gemm_f32(const float* __restrict__ A,
                                                const float* __restrict__ W,
                                                float* __restrict__ C) {
    __shared__ float As[16][65];
    __shared__ float Ws[16][64];
    const int tid = threadIdx.x;
    const int n0 = blockIdx.x * 64, m0 = blockIdx.y * 64;
    const int tx = tid & 15, ty = tid >> 4;
    const int lr = tid >> 2, lk = (tid & 3) * 4;
    const int wr = tid >> 4, wc = (tid & 15) * 4;

    ull acc[4][2];
#pragma unroll
    for (int r = 0; r < 4; ++r) { acc[r][0] = 0ull; acc[r][1] = 0ull; }

    for (int kt = 0; kt < 768; kt += 16) {
        float4 av = *(const float4*)&A[(size_t)(m0 + lr) * 768 + kt + lk];
        *(float4*)&Ws[wr][wc] = *(const float4*)&W[(size_t)(kt + wr) * 768 + n0 + wc];
        As[lk + 0][lr] = av.x; As[lk + 1][lr] = av.y;
        As[lk + 2][lr] = av.z; As[lk + 3][lr] = av.w;
        __syncthreads();
#pragma unroll
        for (int k = 0; k < 16; ++k) {
            ull b0 = *(const ull*)&Ws[k][tx * 4];
            ull b1 = *(const ull*)&Ws[k][tx * 4 + 2];
#pragma unroll
            for (int r = 0; r < 4; ++r) {
                ull a = dupf2(As[k][ty * 4 + r]);
                acc[r][0] = fma2(a, b0, acc[r][0]);
                acc[r][1] = fma2(a, b1, acc[r][1]);
            }
        }
        __syncthreads();
    }
#pragma unroll
    for (int r = 0; r < 4; ++r) {
        float* cp = &C[(size_t)(m0 + ty * 4 + r) * 768 + n0 + tx * 4];
        *(ull*)cp = acc[r][0];
        *(ull*)(cp + 2) = acc[r][1];
    }
}

// ---------------- repack [row, d*12+h] -> [(b*12+h)*S+s][64] ---------------
__global__ __launch_bounds__(256) void repack_head(const float* __restrict__ C,
                                                   float* __restrict__ T) {
    __shared__ float tile[8][768];
    const int tid = threadIdx.x;
    const int row0 = blockIdx.x * 8;
    const int b = row0 >> 11, s0 = row0 & 2047;
    for (int idx = tid; idx < 1536; idx += 256) {
        int r = idx / 192, c = idx % 192;
        *(float4*)&tile[r][c * 4] = *(const float4*)&C[(size_t)(row0 + r) * 768 + c * 4];
    }
    __syncthreads();
    for (int idx = tid; idx < 6144; idx += 256) {
        int h = idx >> 9, rem = idx & 511, ss = rem >> 6, d = rem & 63;
        T[((size_t)(b * 12 + h) * S_ + s0 + ss) * 64 + d] = tile[ss][d * 12 + h];
    }
}

// --------------------------- attention core --------------------------------
// smem: sc[16][2048] | kv[128][66] | q_s[16][64] | rmax[16] | rinv[16]
#define ATTN_SMEM_BYTES ((16 * S_ + 128 * 66 + 16 * 64 + 32) * 4)

__device__ __forceinline__ void load_tile64(const float* __restrict__ src,
                                            float* __restrict__ kv, int tid) {
    const ull* g = (const ull*)src;
    ull* kvU = (ull*)kv;
#pragma unroll 4
    for (int idx = tid; idx < 128 * 32; idx += 256) {
        int r = idx >> 5, c = idx & 31;
        kvU[r * 33 + c] = g[idx];
    }
}

// scores for 16 i-rows vs all 2048 j. 256 threads: warp w -> rows 2w,2w+1.
__device__ __forceinline__ void score_phase(const float* __restrict__ Kbase,
                                            const float* __restrict__ q_s,
                                            float* __restrict__ sc,
                                            float* __restrict__ kv, int tid) {
    const int ii = (tid >> 5) << 1;
    const int jl = tid & 31;
    const ull* q2 = (const ull*)q_s;
    for (int jc = 0; jc < S_; jc += 128) {
        __syncthreads();
        load_tile64(Kbase + (size_t)jc * 64, kv, tid);
        __syncthreads();
        ull acc[8];
#pragma unroll
        for (int t = 0; t < 8; ++t) acc[t] = 0ull;
        const ull* k2 = (const ull*)kv;
#pragma unroll 8
        for (int m = 0; m < 32; ++m) {
            ull a0 = q2[(ii + 0) * 32 + m];
            ull a1 = q2[(ii + 1) * 32 + m];
            ull b0 = k2[(jl) * 33 + m];
            ull b1 = k2[(jl + 32) * 33 + m];
            ull b2 = k2[(jl + 64) * 33 + m];
            ull b3 = k2[(jl + 96) * 33 + m];
            acc[0] = fma2(a0, b0, acc[0]);
            acc[1] = fma2(a0, b1, acc[1]);
            acc[2] = fma2(a0, b2, acc[2]);
            acc[3] = fma2(a0, b3, acc[3]);
            acc[4] = fma2(a1, b0, acc[4]);
            acc[5] = fma2(a1, b1, acc[5]);
            acc[6] = fma2(a1, b2, acc[6]);
            acc[7] = fma2(a1, b3, acc[7]);
        }
#pragma unroll
        for (int r = 0; r < 2; ++r)
#pragma unroll
            for (int c = 0; c < 4; ++c)
                sc[(size_t)(ii + r) * S_ + jc + jl + 32 * c] = sum2(acc[r * 4 + c]) * SCALE_;
    }
}

// exact softmax stats per row (16 rows, 16 lanes each)
__device__ __forceinline__ void softmax_stats(const float* __restrict__ sc,
                                              float* __restrict__ rmax,
                                              float* __restrict__ rinv, int tid) {
    __syncthreads();
    const int r = tid >> 4, l = tid & 15;
    const float* row = sc + (size_t)r * S_;
    float m = -1e30f;
    for (int j = l; j < S_; j += 16) m = fmaxf(m, row[j]);
#pragma unroll
    for (int o = 8; o; o >>= 1) m = fmaxf(m, __shfl_xor_sync(0xffffffffu, m, o));
    float s = 0.f;
    for (int j = l; j < S_; j += 16) s += __expf(row[j] - m);
#pragma unroll
    for (int o = 8; o; o >>= 1) s += __shfl_xor_sync(0xffffffffu, s, o);
    if (l == 0) { rmax[r] = m; rinv[r] = 1.0f / s; }
    __syncthreads();
}

// ---------------- pos-pos attention -> g_posP[h,i,j], grid(128,12) ---------
__global__ __launch_bounds__(256) void attn_pos_kernel() {
    extern __shared__ float smem[];
    float* sc = smem;
    float* kv = sc + 16 * S_;
    float* q_s = kv + 128 * 66;
    float* rmax = q_s + 16 * 64;
    float* rinv = rmax + 16;
    const int tid = threadIdx.x, h = blockIdx.y, i0 = blockIdx.x * 16;

    const ull* gq = (const ull*)(g_qpT + ((size_t)h * S_ + i0) * 64);
    ull* qU = (ull*)q_s;
    for (int idx = tid; idx < 512; idx += 256) qU[idx] = gq[idx];

    score_phase(g_kpT + (size_t)h * S_ * 64, q_s, sc, kv, tid);
    softmax_stats(sc, rmax, rinv, tid);

    for (int idx = tid; idx < 16 * S_; idx += 256) {
        int i = idx >> 11, j = idx & (S_ - 1);
        g_posP[((size_t)h * S_ + i0 + i) * S_ + j] = __expf(sc[idx] - rmax[i]) * rinv[i];
    }
}

// ------- content attention fused: softmax + blend + prob write + P@V -------
// grid(128, 12, 2)
__global__ __launch_bounds__(256) void attn_inp_kernel() {
    extern __shared__ float smem[];
    float* sc = smem;
    float* kv = sc + 16 * S_;
    float* q_s = kv + 128 * 66;
    float* rmax = q_s + 16 * 64;
    float* rinv = rmax + 16;
    const int tid = threadIdx.x;
    const int b = blockIdx.z, h = blockIdx.y, i0 = blockIdx.x * 16;
    const int bh = b * H_ + h;

    const ull* gq = (const ull*)(g_qT + ((size_t)bh * S_ + i0) * 64);
    ull* qU = (ull*)q_s;
    for (int idx = tid; idx < 512; idx += 256) qU[idx] = gq[idx];

    score_phase(g_kT + (size_t)bh * S_ * 64, q_s, sc, kv, tid);
    softmax_stats(sc, rmax, rinv, tid);

    // blend with prob_pos, overwrite sc in place, write [b,h,i,j] coalesced
    for (int idx = tid; idx < 16 * S_; idx += 256) {
        int i = idx >> 11, j = idx & (S_ - 1);
        float p = __expf(sc[idx] - rmax[i]) * rinv[i];
        float pp = __ldg(&g_posP[((size_t)h * S_ + i0 + i) * S_ + j]);
        float bl = 0.5f * (p + pp);
        sc[idx] = bl;
        g_blend[((size_t)bh * S_ + i0 + i) * S_ + j] = bl;
    }

    // P @ V : thread -> 1 row (tid>>4) x 4 d-cols ((tid&15)*4)
    const int ii2 = tid >> 4;
    const int dp = (tid & 15) << 1;  // ull index
    const float* Vb = g_vT + (size_t)bh * S_ * 64;
    ull accv0 = 0ull, accv1 = 0ull;
    for (int jc = 0; jc < S_; jc += 128) {
        __syncthreads();
        load_tile64(Vb + (size_t)jc * 64, kv, tid);
        __syncthreads();
        const ull* v2 = (const ull*)kv;
        const float* pr = sc + (size_t)ii2 * S_ + jc;
#pragma unroll 4
        for (int j = 0; j < 128; ++j) {
            ull pd = dupf2(pr[j]);
            accv0 = fma2(pd, v2[j * 33 + dp], accv0);
            accv1 = fma2(pd, v2[j * 33 + dp + 1], accv1);
        }
    }
    float* o = g_attnpre + (size_t)(b * S_ + i0 + ii2) * 768 + h * 64 + dp * 2;
    *(ull*)o = accv0;
    *(ull*)(o + 2) = accv1;
}

// -------- transpose blended [b,h,i,j] -> out [b,i,j,h], grid(8,2048,2) -----
__global__ __launch_bounds__(256) void transpose_prob(float* __restrict__ outP) {
    __shared__ float tile[12][257];
    const int b = blockIdx.z, i = blockIdx.y, jt = blockIdx.x * 256;
    const int tid = threadIdx.x;
    for (int idx = tid; idx < 12 * 256; idx += 256) {
        int hh = idx >> 8, j = idx & 255;
        tile[hh][j] = g_blend[((size_t)(b * 12 + hh) * S_ + i) * S_ + jt + j];
    }
    __syncthreads();
    float4* dst = (float4*)(outP + ((size_t)(b * S_ + i) * S_ + jt + tid) * 12);
    dst[0] = make_float4(tile[0][tid], tile[1][tid], tile[2][tid], tile[3][tid]);
    dst[1] = make_float4(tile[4][tid], tile[5][tid], tile[6][tid], tile[7][tid]);
    dst[2] = make_float4(tile[8][tid], tile[9][tid], tile[10][tid], tile[11][tid]);
}

// ------------------------------ launcher -----------------------------------
extern "C" void kernel_launch(void* const* d_in, const int* in_sizes, int n_in,
                              void* d_out, int out_size) {
    const float* inp = (const float*)d_in[0];
    const float* pos = (const float*)d_in[1];
    const float* Wqi = (const float*)d_in[2];
    const float* Wki = (const float*)d_in[3];
    const float* Wqp = (const float*)d_in[4];
    const float* Wkp = (const float*)d_in[5];
    const float* Wv  = (const float*)d_in[6];
    const float* Wo  = (const float*)d_in[7];
    float* out = (float*)d_out;

    float *bufQ, *bufK, *bufV, *bufQP, *bufKP, *qT, *kT, *vT, *qpT, *kpT, *pre;
    cudaGetSymbolAddress((void**)&bufQ, g_bufQ);
    cudaGetSymbolAddress((void**)&bufK, g_bufK);
    cudaGetSymbolAddress((void**)&bufV, g_bufV);
    cudaGetSymbolAddress((void**)&bufQP, g_bufQP);
    cudaGetSymbolAddress((void**)&bufKP, g_bufKP);
    cudaGetSymbolAddress((void**)&qT, g_qT);
    cudaGetSymbolAddress((void**)&kT, g_kT);
    cudaGetSymbolAddress((void**)&vT, g_vT);
    cudaGetSymbolAddress((void**)&qpT, g_qpT);
    cudaGetSymbolAddress((void**)&kpT, g_kpT);
    cudaGetSymbolAddress((void**)&pre, g_attnpre);

    static bool attr_done = false;
    if (!attr_done) {
        cudaFuncSetAttribute(attn_pos_kernel,
                             cudaFuncAttributeMaxDynamicSharedMemorySize, ATTN_SMEM_BYTES);
        cudaFuncSetAttribute(attn_inp_kernel,
                             cudaFuncAttributeMaxDynamicSharedMemorySize, ATTN_SMEM_BYTES);
        attr_done = true;
    }

    dim3 g64(12, 64), g32(12, 32);
    gemm_f32<<<g64, 256>>>(inp, Wqi, bufQ);
    gemm_f32<<<g64, 256>>>(inp, Wki, bufK);
    gemm_f32<<<g64, 256>>>(inp, Wv, bufV);
    gemm_f32<<<g32, 256>>>(pos, Wqp, bufQP);
    gemm_f32<<<g32, 256>>>(pos, Wkp, bufKP);

    repack_head<<<512, 256>>>(bufQ, qT);
    repack_head<<<512, 256>>>(bufK, kT);
    repack_head<<<512, 256>>>(bufV, vT);
    repack_head<<<256, 256>>>(bufQP, qpT);
    repack_head<<<256, 256>>>(bufKP, kpT);

    attn_pos_kernel<<<dim3(128, 12), 256, ATTN_SMEM_BYTES>>>();
    attn_inp_kernel<<<dim3(128, 12, 2), 256, ATTN_SMEM_BYTES>>>();

    // outputs: [0, B*S*D) = attn_out, then [B*S*D, ...) = attn_prob [b,i,j,h]
    float* outProb = out + (size_t)B_ * S_ * D_;
    transpose_prob<<<dim3(8, 2048, 2), 256>>>(outProb);

    gemm_f32<<<g64, 256>>>(pre, Wo, out);
}

// round 6
// speedup vs baseline: 2.1645x; 2.1645x over previous
#include <cuda_runtime.h>
#include <cuda_bf16.h>
#include <cstdint>

#define B_ 2
#define S_ 2048
#define D_ 768
#define H_ 12
#define DH_ 64
#define NBH_ (B_ * H_)
#define SCALE_ 0.125f

typedef unsigned long long ull;

// ============================ device scratch ================================
__device__ float g_bufQ[B_ * S_ * D_];
__device__ float g_bufK[B_ * S_ * D_];
__device__ float g_bufV[B_ * S_ * D_];
__device__ float g_bufQP[S_ * D_];
__device__ float g_bufKP[S_ * D_];

__device__ float g_qT[NBH_ * S_ * DH_];    // [bh, s, d]
__device__ float g_vT[NBH_ * S_ * DH_];    // [bh, s, d]
__device__ float g_kTg[NBH_ * DH_ * S_];   // [bh, d, s] (transposed)
__device__ float g_qpT[H_ * S_ * DH_];
__device__ float g_kpTg[H_ * DH_ * S_];

__device__ float g_scoreC[(size_t)NBH_ * S_ * S_];  // scaled scores [bh,i,j]
__device__ float g_scoreP[(size_t)H_ * S_ * S_];    // scaled pos scores [h,i,j]
__device__ float2 g_statsC[NBH_ * S_];              // (max, sum)
__device__ float2 g_statsP[H_ * S_];
__device__ float g_blend[(size_t)NBH_ * S_ * S_];   // blended prob fp32 [bh,i,j]
__device__ float g_attnpre[B_ * S_ * D_];           // [b, s, h*64+d]

// --------------------------- f32x2 helpers ---------------------------------
__device__ __forceinline__ ull fma2(ull a, ull b, ull c) {
    ull d; asm("fma.rn.f32x2 %0, %1, %2, %3;" : "=l"(d) : "l"(a), "l"(b), "l"(c));
    return d;
}
__device__ __forceinline__ ull dupf2(float x) {
    ull d; asm("mov.b64 %0, {%1, %1};" : "=l"(d) : "f"(x));
    return d;
}
__device__ __forceinline__ ull pack2(float x, float y) {
    ull d; asm("mov.b64 %0, {%1, %2};" : "=l"(d) : "f"(x), "f"(y));
    return d;
}
__device__ __forceinline__ float lo2(ull v) { return __uint_as_float((unsigned)v); }
__device__ __forceinline__ float hi2(ull v) { return __uint_as_float((unsigned)(v >> 32)); }

// ================== GEMM: C[M,768] = A[M,768] @ W[768,768] =================
// 128x128 block tile, BK=16, 256 threads, 8x8 outputs/thread (8 rows x 4 ull).
// W staged in smem as [k][c][tx] ull-blocks -> conflict-free LDS.64.
__global__ __launch_bounds__(256) void gemm_multi(
    const float* __restrict__ A,
    const float* __restrict__ W0, const float* __restrict__ W1, const float* __restrict__ W2,
    float* __restrict__ C0, float* __restrict__ C1, float* __restrict__ C2,
    int ntiles_per) {
    __shared__ float As[16 * 130];   // [k][m] transposed
    __shared__ ull Ws[16 * 64];      // [k][c*16+tx]
    const int tid = threadIdx.x;
    const int sel = blockIdx.x / ntiles_per;
    const int nt = blockIdx.x % ntiles_per;
    const float* W = sel == 0 ? W0 : (sel == 1 ? W1 : W2);
    float* C = sel == 0 ? C0 : (sel == 1 ? C1 : C2);
    const int n0 = nt * 128, m0 = blockIdx.y * 128;
    const int tx = tid & 15, ty = tid >> 4;

    ull acc[8][4];
#pragma unroll
    for (int r = 0; r < 8; ++r)
#pragma unroll
        for (int c = 0; c < 4; ++c) acc[r][c] = 0ull;

    for (int kt = 0; kt < 768; kt += 16) {
        __syncthreads();
#pragma unroll
        for (int ii = 0; ii < 2; ++ii) {
            int idx = tid + ii * 256;
            int row = idx >> 2, kg = idx & 3;
            float4 a = *(const float4*)&A[(size_t)(m0 + row) * 768 + kt + kg * 4];
            As[(kg * 4 + 0) * 130 + row] = a.x;
            As[(kg * 4 + 1) * 130 + row] = a.y;
            As[(kg * 4 + 2) * 130 + row] = a.z;
            As[(kg * 4 + 3) * 130 + row] = a.w;
        }
#pragma unroll
        for (int ii = 0; ii < 2; ++ii) {
            int idx = tid + ii * 256;
            int wr = idx >> 5, wq = idx & 31;
            float4 w = *(const float4*)&W[(size_t)(kt + wr) * 768 + n0 + wq * 4];
            int p = wq * 2, c = p >> 4, x = p & 15;
            Ws[(wr * 4 + c) * 16 + x] = pack2(w.x, w.y);
            Ws[(wr * 4 + c) * 16 + x + 1] = pack2(w.z, w.w);
        }
        __syncthreads();
#pragma unroll
        for (int k = 0; k < 16; ++k) {
            ull b0 = Ws[(k * 4 + 0) * 16 + tx];
            ull b1 = Ws[(k * 4 + 1) * 16 + tx];
            ull b2 = Ws[(k * 4 + 2) * 16 + tx];
            ull b3 = Ws[(k * 4 + 3) * 16 + tx];
#pragma unroll
            for (int r = 0; r < 8; ++r) {
                ull a = dupf2(As[k * 130 + ty * 8 + r]);
                acc[r][0] = fma2(a, b0, acc[r][0]);
                acc[r][1] = fma2(a, b1, acc[r][1]);
                acc[r][2] = fma2(a, b2, acc[r][2]);
                acc[r][3] = fma2(a, b3, acc[r][3]);
            }
        }
    }
#pragma unroll
    for (int r = 0; r < 8; ++r)
#pragma unroll
        for (int c = 0; c < 4; ++c)
            *(ull*)&C[(size_t)(m0 + ty * 8 + r) * 768 + n0 + c * 32 + tx * 2] = acc[r][c];
}

// ============ repack [row, d*12+h] -> [bh, s, d] (row-major) ================
__global__ __launch_bounds__(256) void repack_head(const float* __restrict__ C,
                                                   float* __restrict__ T) {
    __shared__ float tile[8 * 768];
    const int tid = threadIdx.x;
    const int row0 = blockIdx.x * 8;
    const int b = row0 >> 11, s0 = row0 & 2047;
    for (int idx = tid; idx < 1536; idx += 256)
        *(float4*)&tile[idx * 4] = *(const float4*)&C[(size_t)row0 * 768 + idx * 4];
    __syncthreads();
    for (int idx = tid; idx < 6144; idx += 256) {
        int h = idx >> 9, rem = idx & 511, ss = rem >> 6, d = rem & 63;
        T[((size_t)(b * 12 + h) * S_ + s0 + ss) * 64 + d] = tile[ss * 768 + d * 12 + h];
    }
}

// ============ repack [row, d*12+h] -> transposed [bh, d, s] =================
__global__ __launch_bounds__(256) void repack_kt(const float* __restrict__ C,
                                                 float* __restrict__ T) {
    extern __shared__ float tile[];   // 32 * 768 floats = 96KB
    const int tid = threadIdx.x;
    const int row0 = blockIdx.x * 32;
    const int b = row0 >> 11, s0 = row0 & 2047;
    for (int idx = tid; idx < 6144; idx += 256)
        *(float4*)&tile[idx * 4] = *(const float4*)&C[(size_t)row0 * 768 + idx * 4];
    __syncthreads();
    for (int pp = tid; pp < 768; pp += 256) {
        int h = pp >> 6, d = pp & 63;
        size_t base = ((size_t)(b * 12 + h) * 64 + d) * S_ + s0;
#pragma unroll 8
        for (int ss = 0; ss < 32; ++ss)
            T[base + ss] = tile[ss * 768 + d * 12 + h];
    }
}

// =========================== score kernel ===================================
// grid (16, G), 256 threads. i-tile = 128, j-chunks of 128.
// Per-thread 8 rows x 8 cols (4 ull). Online (max,sum) per row, reduced at end.
// smem: qs [128][68] fp32 (34816 B) | kb [64][4][16] ull (32768 B)
#define SCK_SMEM (34816 + 32768)
__global__ __launch_bounds__(256) void score_kernel(
    const float* __restrict__ Q,    // [G, S, 64]
    const float* __restrict__ KT,   // [G, 64, S]
    float* __restrict__ outS,       // [G, S, S]
    float2* __restrict__ stats) {   // [G, S]
    extern __shared__ char smem[];
    float* qs = (float*)smem;
    ull* kb = (ull*)(smem + 34816);
    const int tid = threadIdx.x;
    const int tx = tid & 15, ty = tid >> 4;
    const int i0 = blockIdx.x * 128, g = blockIdx.y;

    const float* Qg = Q + ((size_t)g * S_ + i0) * 64;
    for (int idx = tid; idx < 2048; idx += 256) {
        int r = idx >> 4, dq = idx & 15;
        *(float4*)&qs[r * 68 + dq * 4] = *(const float4*)&Qg[(size_t)r * 64 + dq * 4];
    }

    float m_r[8], s_r[8];
#pragma unroll
    for (int r = 0; r < 8; ++r) { m_r[r] = -1e30f; s_r[r] = 0.f; }

    const float* KTg = KT + (size_t)g * 64 * S_;
    float* outp = outS + (size_t)g * S_ * S_;

    for (int jt = 0; jt < 16; ++jt) {
        const int j0 = jt * 128;
        __syncthreads();
        for (int idx = tid; idx < 2048; idx += 256) {   // 64 d x 32 float4
            int d = idx >> 5, jq = idx & 31;
            float4 v = *(const float4*)&KTg[(size_t)d * S_ + j0 + jq * 4];
            int p = jq * 2, c = p >> 4, x = p & 15;
            kb[(d * 4 + c) * 16 + x] = pack2(v.x, v.y);
            kb[(d * 4 + c) * 16 + x + 1] = pack2(v.z, v.w);
        }
        __syncthreads();

        ull acc[8][4];
#pragma unroll
        for (int r = 0; r < 8; ++r)
#pragma unroll
            for (int c = 0; c < 4; ++c) acc[r][c] = 0ull;

#pragma unroll 4
        for (int d = 0; d < 64; ++d) {
            ull b0 = kb[(d * 4 + 0) * 16 + tx];
            ull b1 = kb[(d * 4 + 1) * 16 + tx];
            ull b2 = kb[(d * 4 + 2) * 16 + tx];
            ull b3 = kb[(d * 4 + 3) * 16 + tx];
            const float* qrow = qs + d;
#pragma unroll
            for (int r = 0; r < 8; ++r) {
                ull a = dupf2(qrow[(ty * 8 + r) * 68]);
                acc[r][0] = fma2(a, b0, acc[r][0]);
                acc[r][1] = fma2(a, b1, acc[r][1]);
                acc[r][2] = fma2(a, b2, acc[r][2]);
                acc[r][3] = fma2(a, b3, acc[r][3]);
            }
        }

        // epilogue: scale, online stats, store
#pragma unroll
        for (int r = 0; r < 8; ++r) {
            float v[8];
#pragma unroll
            for (int c = 0; c < 4; ++c) {
                v[2 * c] = lo2(acc[r][c]) * SCALE_;
                v[2 * c + 1] = hi2(acc[r][c]) * SCALE_;
            }
            float cm = v[0];
#pragma unroll
            for (int t = 1; t < 8; ++t) cm = fmaxf(cm, v[t]);
            float mN = fmaxf(m_r[r], cm);
            float add = 0.f;
#pragma unroll
            for (int t = 0; t < 8; ++t) add += __expf(v[t] - mN);
            s_r[r] = s_r[r] * __expf(m_r[r] - mN) + add;
            m_r[r] = mN;
            size_t ro = (size_t)(i0 + ty * 8 + r) * S_ + j0;
#pragma unroll
            for (int c = 0; c < 4; ++c)
                *(ull*)&outp[ro + c * 32 + tx * 2] = pack2(v[2 * c], v[2 * c + 1]);
        }
    }

    // reduce stats across the 16 tx threads of each row
    __syncthreads();
    float2* st = (float2*)(smem + 34816);   // reuse kb (16 KB needed)
#pragma unroll
    for (int r = 0; r < 8; ++r)
        st[(ty * 8 + r) * 16 + tx] = make_float2(m_r[r], s_r[r]);
    __syncthreads();
    if (tid < 128) {
        float m = -1e30f;
#pragma unroll
        for (int t = 0; t < 16; ++t) m = fmaxf(m, st[tid * 16 + t].x);
        float s = 0.f;
#pragma unroll
        for (int t = 0; t < 16; ++t) {
            float2 p = st[tid * 16 + t];
            s += p.y * __expf(p.x - m);
        }
        stats[(size_t)g * S_ + i0 + tid] = make_float2(m, s);
    }
}

// ====== blend: softmax + gamma-mix + prob output + fp32 blend buffer =======
// grid (S_, B_), 256 threads
__global__ __launch_bounds__(256) void blend_kernel(float* __restrict__ outP) {
    __shared__ float stage[12][257];
    __shared__ float smx[12], sinv[12], pmx[12], pinv[12];
    const int i = blockIdx.x, b = blockIdx.y, tid = threadIdx.x;
    if (tid < 12) {
        float2 sc = g_statsC[(b * 12 + tid) * S_ + i];
        smx[tid] = sc.x; sinv[tid] = 1.0f / sc.y;
        float2 sp = g_statsP[tid * S_ + i];
        pmx[tid] = sp.x; pinv[tid] = 1.0f / sp.y;
    }
    __syncthreads();
    for (int jc = 0; jc < S_; jc += 256) {
        const int j = jc + tid;
#pragma unroll 1
        for (int h = 0; h < 12; ++h) {
            size_t idxC = ((size_t)(b * 12 + h) * S_ + i) * S_ + j;
            float p = __expf(g_scoreC[idxC] - smx[h]) * sinv[h];
            float pp = __expf(g_scoreP[((size_t)h * S_ + i) * S_ + j] - pmx[h]) * pinv[h];
            float bl = 0.5f * (p + pp);
            g_blend[idxC] = bl;
            stage[h][tid] = bl;
        }
        __syncthreads();
        float4* dst = (float4*)(outP + (((size_t)b * S_ + i) * S_ + j) * 12);
        dst[0] = make_float4(stage[0][tid], stage[1][tid], stage[2][tid], stage[3][tid]);
        dst[1] = make_float4(stage[4][tid], stage[5][tid], stage[6][tid], stage[7][tid]);
        dst[2] = make_float4(stage[8][tid], stage[9][tid], stage[10][tid], stage[11][tid]);
        __syncthreads();
    }
}

// ============================ AV kernel =====================================
// grid (16, NBH_), 128 threads. 128 i-rows x 64 d per block.
// Thread tile 8 rows x 4 ull (8 d). smem: ps [128][132] | vs [128][4][8] ull.
#define AV_SMEM (67584 + 32768)
__global__ __launch_bounds__(128) void av_kernel() {
    extern __shared__ char smem[];
    float* ps = (float*)smem;
    ull* vs = (ull*)(smem + 67584);
    const int tid = threadIdx.x;
    const int tx = tid & 7, ty = tid >> 3;   // 16 ty x 8 tx
    const int i0 = blockIdx.x * 128, bh = blockIdx.y;
    const int b = bh / 12, h = bh % 12;

    ull acc[8][4];
#pragma unroll
    for (int r = 0; r < 8; ++r)
#pragma unroll
        for (int c = 0; c < 4; ++c) acc[r][c] = 0ull;

    const float* Pg = g_blend + (size_t)bh * S_ * S_;
    const float* Vg = g_vT + (size_t)bh * S_ * 64;

    for (int jt = 0; jt < 16; ++jt) {
        const int j0 = jt * 128;
        __syncthreads();
        for (int idx = tid; idx < 4096; idx += 128) {   // P: 128 x 32 float4
            int r = idx >> 5, jq = idx & 31;
            *(float4*)&ps[r * 132 + jq * 4] =
                *(const float4*)&Pg[(size_t)(i0 + r) * S_ + j0 + jq * 4];
        }
        for (int idx = tid; idx < 2048; idx += 128) {   // V: 128 x 16 float4
            int s = idx >> 4, dq = idx & 15;
            float4 v = *(const float4*)&Vg[(size_t)(j0 + s) * 64 + dq * 4];
            int p = dq * 2, c = p >> 3, x = p & 7;
            vs[(s * 4 + c) * 8 + x] = pack2(v.x, v.y);
            vs[(s * 4 + c) * 8 + x + 1] = pack2(v.z, v.w);
        }
        __syncthreads();
#pragma unroll 4
        for (int j = 0; j < 128; ++j) {
            ull b0 = vs[(j * 4 + 0) * 8 + tx];
            ull b1 = vs[(j * 4 + 1) * 8 + tx];
            ull b2 = vs[(j * 4 + 2) * 8 + tx];
            ull b3 = vs[(j * 4 + 3) * 8 + tx];
            const float* pcol = ps + j;
#pragma unroll
            for (int r = 0; r < 8; ++r) {
                ull a = dupf2(pcol[(ty * 8 + r) * 132]);
                acc[r][0] = fma2(a, b0, acc[r][0]);
                acc[r][1] = fma2(a, b1, acc[r][1]);
                acc[r][2] = fma2(a, b2, acc[r][2]);
                acc[r][3] = fma2(a, b3, acc[r][3]);
            }
        }
    }
#pragma unroll
    for (int r = 0; r < 8; ++r)
#pragma unroll
        for (int c = 0; c < 4; ++c)
            *(ull*)&g_attnpre[(size_t)(b * S_ + i0 + ty * 8 + r) * 768 +
                              h * 64 + c * 16 + tx * 2] = acc[r][c];
}

// ============================== launcher ====================================
extern "C" void kernel_launch(void* const* d_in, const int* in_sizes, int n_in,
                              void* d_out, int out_size) {
    const float* inp = (const float*)d_in[0];
    const float* pos = (const float*)d_in[1];
    const float* Wqi = (const float*)d_in[2];
    const float* Wki = (const float*)d_in[3];
    const float* Wqp = (const float*)d_in[4];
    const float* Wkp = (const float*)d_in[5];
    const float* Wv  = (const float*)d_in[6];
    const float* Wo  = (const float*)d_in[7];
    float* out = (float*)d_out;

    float *bufQ, *bufK, *bufV, *bufQP, *bufKP;
    float *qT, *vT, *kTg, *qpT, *kpTg, *pre, *scC, *scP;
    float2 *stC, *stP;
    cudaGetSymbolAddress((void**)&bufQ, g_bufQ);
    cudaGetSymbolAddress((void**)&bufK, g_bufK);
    cudaGetSymbolAddress((void**)&bufV, g_bufV);
    cudaGetSymbolAddress((void**)&bufQP, g_bufQP);
    cudaGetSymbolAddress((void**)&bufKP, g_bufKP);
    cudaGetSymbolAddress((void**)&qT, g_qT);
    cudaGetSymbolAddress((void**)&vT, g_vT);
    cudaGetSymbolAddress((void**)&kTg, g_kTg);
    cudaGetSymbolAddress((void**)&qpT, g_qpT);
    cudaGetSymbolAddress((void**)&kpTg, g_kpTg);
    cudaGetSymbolAddress((void**)&pre, g_attnpre);
    cudaGetSymbolAddress((void**)&scC, g_scoreC);
    cudaGetSymbolAddress((void**)&scP, g_scoreP);
    cudaGetSymbolAddress((void**)&stC, g_statsC);
    cudaGetSymbolAddress((void**)&stP, g_statsP);

    static bool attr_done = false;
    if (!attr_done) {
        cudaFuncSetAttribute(score_kernel, cudaFuncAttributeMaxDynamicSharedMemorySize, SCK_SMEM);
        cudaFuncSetAttribute(av_kernel, cudaFuncAttributeMaxDynamicSharedMemorySize, AV_SMEM);
        cudaFuncSetAttribute(repack_kt, cudaFuncAttributeMaxDynamicSharedMemorySize, 32 * 768 * 4);
        attr_done = true;
    }

    // projections (QKV fused; pos Q/K fused)
    gemm_multi<<<dim3(18, 32), 256>>>(inp, Wqi, Wki, Wv, bufQ, bufK, bufV, 6);
    gemm_multi<<<dim3(12, 16), 256>>>(pos, Wqp, Wkp, Wkp, bufQP, bufKP, bufKP, 6);

    // repack
    repack_head<<<512, 256>>>(bufQ, qT);
    repack_head<<<512, 256>>>(bufV, vT);
    repack_kt<<<128, 256, 32 * 768 * 4>>>(bufK, kTg);
    repack_head<<<256, 256>>>(bufQP, qpT);
    repack_kt<<<64, 256, 32 * 768 * 4>>>(bufKP, kpTg);

    // scores + stats
    score_kernel<<<dim3(16, NBH_), 256, SCK_SMEM>>>(qT, kTg, scC, stC);
    score_kernel<<<dim3(16, H_), 256, SCK_SMEM>>>(qpT, kpTg, scP, stP);

    // softmax + blend + prob output [b,i,j,h]
    float* outProb = out + (size_t)B_ * S_ * D_;
    blend_kernel<<<dim3(S_, B_), 256>>>(outProb);

    // P @ V
    av_kernel<<<dim3(16, NBH_), 128, AV_SMEM>>>();

    // final projection
    gemm_multi<<<dim3(6, 32), 256>>>(pre, Wo, Wo, Wo, out, out, out, 6);
}